// round 2
// baseline (speedup 1.0000x reference)
#include <cuda_runtime.h>
#include <cstdint>

#define DEVINL __device__ __forceinline__

// Problem shape (fixed)
static constexpr int Bn   = 32;
static constexpr int Cc   = 128;
static constexpr int Hs   = 56;
static constexpr int Wsp  = 56;
static constexpr int Ff   = 128;
static constexpr int HWn  = Hs * Wsp;      // 3136
static constexpr int Ktot = Cc * 9;        // 1152
static constexpr int KC   = 32;            // K chunk
static constexpr int NCH  = Ktot / KC;     // 36
static constexpr int MT   = 128;           // M tile
static constexpr int Mtot = Bn * HWn;      // 100352
static constexpr int GRID = Mtot / MT;     // 784 exact

// smem: two stages of [A(128x32 f32) | B(128x32 f32)] = 2 * 32KB
static constexpr int A_BYTES   = MT * KC * 4;        // 16384
static constexpr int STG_BYTES = 2 * A_BYTES;        // 32768
static constexpr int DSMEM     = 2 * STG_BYTES + 128;  // + alignment slack

// swizzled offset inside a 128B-row tile: col4 is byte offset within row
DEVINL uint32_t tile_off(int row, int col4) {
    return (uint32_t)(row * 128 + (col4 ^ ((row & 7) << 4)));
}

DEVINL uint32_t smem_u32(const void* p) {
    uint32_t a;
    asm("{ .reg .u64 t; cvta.to.shared.u64 t, %1; cvt.u32.u64 %0, t; }"
        : "=r"(a) : "l"(p));
    return a;
}

DEVINL void cp_async4(uint32_t dst, const void* src, uint32_t sz) {
    asm volatile("cp.async.ca.shared.global [%0], [%1], 4, %2;"
                 :: "r"(dst), "l"(src), "r"(sz) : "memory");
}
DEVINL void cp_commit() { asm volatile("cp.async.commit_group;" ::: "memory"); }
template <int N> DEVINL void cp_wait() {
    asm volatile("cp.async.wait_group %0;" :: "n"(N) : "memory");
}

DEVINL void ldsm4(uint32_t& r0, uint32_t& r1, uint32_t& r2, uint32_t& r3,
                  uint32_t addr) {
    asm volatile("ldmatrix.sync.aligned.m8n8.x4.shared.b16 {%0,%1,%2,%3}, [%4];"
                 : "=r"(r0), "=r"(r1), "=r"(r2), "=r"(r3) : "r"(addr));
}

DEVINL void to_tf32(uint32_t& r) {
    asm("cvt.rna.tf32.f32 %0, %0;" : "+r"(r));
}

DEVINL void mma_tf32(float& d0, float& d1, float& d2, float& d3,
                     uint32_t a0, uint32_t a1, uint32_t a2, uint32_t a3,
                     uint32_t b0, uint32_t b1) {
    asm volatile(
        "mma.sync.aligned.m16n8k8.row.col.f32.tf32.tf32.f32 "
        "{%0,%1,%2,%3}, {%4,%5,%6,%7}, {%8,%9}, {%0,%1,%2,%3};"
        : "+f"(d0), "+f"(d1), "+f"(d2), "+f"(d3)
        : "r"(a0), "r"(a1), "r"(a2), "r"(a3), "r"(b0), "r"(b1));
}

// ---------------------------------------------------------------------------
// Implicit-GEMM 3x3 SAME conv:
//   A[m][k] = x[b, c, h+kh-1, w+kw-1]  (k = c*9 + kh*3 + kw, zero pad)
//   Bt[n][k] = W[k][n]
//   D = A @ Bt^T ; out[p*128+f] = min(D + (1 - Di[f]), 1)   (NHWC)
// CTA tile 128x128, K-chunk 32, cp.async double buffer, mma.sync tf32.
// ---------------------------------------------------------------------------

extern "C" __global__ void __launch_bounds__(256, 2)
spiking_conv_kernel(const float* __restrict__ x, const float* __restrict__ Wm,
                    const float* __restrict__ Di, float* __restrict__ out)
{
    extern __shared__ char smraw[];
    __shared__ float thr[Ff];

    const uint32_t sm_base = (smem_u32(smraw) + 127u) & ~127u;
    const int tid  = threadIdx.x;
    const int wid  = tid >> 5;
    const int lane = tid & 31;
    const int tile = blockIdx.x;

    if (tid < Ff) thr[tid] = 1.0f - Di[tid];

    // ---- per-thread loader state -------------------------------------------
    // A writer: lane = k column, rows = wid + 8*i  (i < 16)
    int qbase[16];   // b*C*HW + h*W + w
    int hh[16], ww[16];
#pragma unroll
    for (int i = 0; i < 16; i++) {
        int m = wid + 8 * i;
        int p = tile * MT + m;
        int b = p / HWn; int s = p - b * HWn;
        int h = s / Wsp; int w = s - h * Wsp;
        qbase[i] = b * (Cc * HWn) + h * Wsp + w;
        hh[i] = h; ww[i] = w;
    }
    // B writer: k = 4*wid + (lane&3), n = (lane>>2) + 8*nb
    const int bk  = 4 * wid + (lane & 3);
    const int bnq = lane >> 2;

    // ---- async load of one K-chunk into stage buffer -----------------------
    auto issue = [&](int ch) {
        const uint32_t abuf = sm_base + (uint32_t)((ch & 1) * STG_BYTES);
        const uint32_t bbuf = abuf + (uint32_t)A_BYTES;
        const int k0 = ch * KC;

        // A: im2col gather (zero-filled padding via src-size=0)
        {
            const int kg = k0 + lane;
            const int c  = kg / 9;
            const int t  = kg - c * 9;
            const int dh = t / 3 - 1;
            const int dw = t - (t / 3) * 3 - 1;
            const int coff = c * HWn + dh * Wsp + dw;
            const uint32_t colb = (uint32_t)(lane * 4);
#pragma unroll
            for (int i = 0; i < 16; i++) {
                const int row = wid + 8 * i;
                bool ok = (unsigned)(hh[i] + dh) < (unsigned)Hs &&
                          (unsigned)(ww[i] + dw) < (unsigned)Wsp;
                const float* src = ok ? (x + coff + qbase[i]) : x;
                cp_async4(abuf + tile_off(row, (int)colb), src, ok ? 4u : 0u);
            }
        }
        // B: Wt[n][k] = W[k0+bk][n]
        {
            const float* srcW = Wm + (size_t)(k0 + bk) * Ff + bnq;
            const uint32_t colb = (uint32_t)(bk * 4);
#pragma unroll
            for (int nb = 0; nb < 16; nb++) {
                const int n = bnq + 8 * nb;
                cp_async4(bbuf + tile_off(n, (int)colb), srcW + 8 * nb, 4u);
            }
        }
        cp_commit();
    };

    // ---- warp MMA geometry --------------------------------------------------
    const int wm = (wid & 3) * 32;   // warp M origin (4 warps along M)
    const int wn = (wid >> 2) * 64;  // warp N origin (2 warps along N)

    float acc[2][8][4];
#pragma unroll
    for (int mt = 0; mt < 2; mt++)
#pragma unroll
        for (int nt = 0; nt < 8; nt++)
#pragma unroll
            for (int r = 0; r < 4; r++) acc[mt][nt][r] = 0.0f;

    // ldmatrix lane->address components (fixed per thread)
    const int a_row_l = lane & 15;              // + mbase
    const int a_col_l = (lane & 16) ? 16 : 0;   // + ks*32
    const int b_row_l = (lane & 7) + ((lane & 16) ? 8 : 0);  // + nbase
    const int b_col_l = (lane & 8) ? 16 : 0;    // + ks*32

    issue(0);

    for (int ch = 0; ch < NCH; ch++) {
        if (ch + 1 < NCH) issue(ch + 1);
        if (ch + 1 < NCH) cp_wait<1>(); else cp_wait<0>();
        __syncthreads();

        const uint32_t abuf = sm_base + (uint32_t)((ch & 1) * STG_BYTES);
        const uint32_t bbuf = abuf + (uint32_t)A_BYTES;

#pragma unroll
        for (int ks = 0; ks < 4; ks++) {
            uint32_t af[2][4];
#pragma unroll
            for (int mt = 0; mt < 2; mt++) {
                const int row = wm + mt * 16 + a_row_l;
                ldsm4(af[mt][0], af[mt][1], af[mt][2], af[mt][3],
                      abuf + tile_off(row, ks * 32 + a_col_l));
                to_tf32(af[mt][0]); to_tf32(af[mt][1]);
                to_tf32(af[mt][2]); to_tf32(af[mt][3]);
            }
            uint32_t bf[4][4];
#pragma unroll
            for (int tp = 0; tp < 4; tp++) {
                const int row = wn + tp * 16 + b_row_l;
                ldsm4(bf[tp][0], bf[tp][1], bf[tp][2], bf[tp][3],
                      bbuf + tile_off(row, ks * 32 + b_col_l));
                to_tf32(bf[tp][0]); to_tf32(bf[tp][1]);
                to_tf32(bf[tp][2]); to_tf32(bf[tp][3]);
            }
#pragma unroll
            for (int mt = 0; mt < 2; mt++)
#pragma unroll
                for (int nt = 0; nt < 8; nt++) {
                    const uint32_t b0 = bf[nt >> 1][(nt & 1) * 2 + 0];
                    const uint32_t b1 = bf[nt >> 1][(nt & 1) * 2 + 1];
                    mma_tf32(acc[mt][nt][0], acc[mt][nt][1],
                             acc[mt][nt][2], acc[mt][nt][3],
                             af[mt][0], af[mt][1], af[mt][2], af[mt][3],
                             b0, b1);
                }
        }
        __syncthreads();   // all warps done reading stage before it refills
    }

    // ---- epilogue: bias + clamp, NHWC f32 stores ---------------------------
    const int gid  = lane >> 2;       // groupID
    const int tig  = lane & 3;        // thread in group
#pragma unroll
    for (int mt = 0; mt < 2; mt++) {
        const int m0 = wm + mt * 16 + gid;
        const int p0 = tile * MT + m0;
        float* o0 = out + (size_t)p0 * Ff;
        float* o1 = o0 + 8 * Ff;      // rows +8 (c2,c3)
#pragma unroll
        for (int nt = 0; nt < 8; nt++) {
            const int f = wn + nt * 8 + tig * 2;
            float2 v0, v1;
            v0.x = fminf(acc[mt][nt][0] + thr[f],     1.0f);
            v0.y = fminf(acc[mt][nt][1] + thr[f + 1], 1.0f);
            v1.x = fminf(acc[mt][nt][2] + thr[f],     1.0f);
            v1.y = fminf(acc[mt][nt][3] + thr[f + 1], 1.0f);
            *reinterpret_cast<float2*>(o0 + f) = v0;
            *reinterpret_cast<float2*>(o1 + f) = v1;
        }
    }
}

// ------------------------------- launcher -----------------------------------

extern "C" void kernel_launch(void* const* d_in, const int* in_sizes, int n_in,
                              void* d_out, int out_size) {
    const float* tj = (const float*)d_in[0];   // [32,128,56,56]
    const float* Wm = (const float*)d_in[1];   // [1152,128]
    const float* Di = (const float*)d_in[2];   // [9,128] (row 0 used)
    float* out = (float*)d_out;                // [32,56,56,128]

    cudaFuncSetAttribute(spiking_conv_kernel,
                         cudaFuncAttributeMaxDynamicSharedMemorySize, DSMEM);
    spiking_conv_kernel<<<GRID, 256, DSMEM>>>(tj, Wm, Di, out);
}

// round 5
// speedup vs baseline: 1.2067x; 1.2067x over previous
#include <cuda_runtime.h>
#include <cstdint>

#define DEVINL __device__ __forceinline__

// Problem shape (fixed)
static constexpr int Bn   = 32;
static constexpr int Cc   = 128;
static constexpr int Hs   = 56;
static constexpr int Wsp  = 56;
static constexpr int Ff   = 128;
static constexpr int HWn  = Hs * Wsp;      // 3136
static constexpr int Ktot = Cc * 9;        // 1152
static constexpr int KC   = 32;            // K chunk
static constexpr int NCH  = Ktot / KC;     // 36
static constexpr int MT   = 128;           // M tile
static constexpr int Mtot = Bn * HWn;      // 100352
static constexpr int GRID = Mtot / MT;     // 784 exact

// smem: two stages of [A(128x32 f32) | B(128x32 f32)] = 2 * 32KB
static constexpr int A_BYTES   = MT * KC * 4;          // 16384
static constexpr int STG_BYTES = 2 * A_BYTES;          // 32768
static constexpr int DSMEM     = 2 * STG_BYTES + 128;

// swizzled offset inside a 128B-row tile
DEVINL uint32_t tile_off(int row, int col4) {
    return (uint32_t)(row * 128 + (col4 ^ ((row & 7) << 4)));
}

DEVINL uint32_t smem_u32(const void* p) {
    uint32_t a;
    asm("{ .reg .u64 t; cvta.to.shared.u64 t, %1; cvt.u32.u64 %0, t; }"
        : "=r"(a) : "l"(p));
    return a;
}

DEVINL void cp_async4(uint32_t dst, const void* src, uint32_t sz) {
    asm volatile("cp.async.ca.shared.global [%0], [%1], 4, %2;"
                 :: "r"(dst), "l"(src), "r"(sz) : "memory");
}
DEVINL void cp_commit() { asm volatile("cp.async.commit_group;" ::: "memory"); }
template <int N> DEVINL void cp_wait() {
    asm volatile("cp.async.wait_group %0;" :: "n"(N) : "memory");
}

DEVINL void ldsm4(uint32_t& r0, uint32_t& r1, uint32_t& r2, uint32_t& r3,
                  uint32_t addr) {
    asm volatile("ldmatrix.sync.aligned.m8n8.x4.shared.b16 {%0,%1,%2,%3}, [%4];"
                 : "=r"(r0), "=r"(r1), "=r"(r2), "=r"(r3) : "r"(addr));
}

DEVINL void mma_tf32(float& d0, float& d1, float& d2, float& d3,
                     uint32_t a0, uint32_t a1, uint32_t a2, uint32_t a3,
                     uint32_t b0, uint32_t b1) {
    asm volatile(
        "mma.sync.aligned.m16n8k8.row.col.f32.tf32.tf32.f32 "
        "{%0,%1,%2,%3}, {%4,%5,%6,%7}, {%8,%9}, {%0,%1,%2,%3};"
        : "+f"(d0), "+f"(d1), "+f"(d2), "+f"(d3)
        : "r"(a0), "r"(a1), "r"(a2), "r"(a3), "r"(b0), "r"(b1));
}

// ---------------------------------------------------------------------------
// Implicit-GEMM 3x3 SAME conv, CTA tile 128x128, K-chunk 32, cp.async double
// buffer, mma.sync tf32 (raw fp32 bits; HW truncation).
//
// Loader mapping: lane -> contiguous m (or n), loop -> k. Each cp.async
// instruction reads 128B of contiguous global memory (1-2 L1 wavefronts).
// ---------------------------------------------------------------------------

extern "C" __global__ void __launch_bounds__(256, 2)
spiking_conv_kernel(const float* __restrict__ x, const float* __restrict__ Wm,
                    const float* __restrict__ Di, float* __restrict__ out)
{
    extern __shared__ char smraw[];
    __shared__ float thr[Ff];

    const uint32_t sm_base = (smem_u32(smraw) + 127u) & ~127u;
    const int tid  = threadIdx.x;
    const int wid  = tid >> 5;
    const int lane = tid & 31;
    const int tile = blockIdx.x;

    if (tid < Ff) thr[tid] = 1.0f - Di[tid];

    // ---- loader state: one fixed m (and n) per thread ----------------------
    // warp w: rows 32*(w&3).., k-halves 16*(w>>2)..
    const int lrow  = 32 * (wid & 3) + lane;    // m for A, n for B
    const int kbase = 16 * (wid >> 2);          // k offset within chunk

    const int pA = tile * MT + lrow;
    const int bA = pA / HWn;  const int sA = pA - bA * HWn;
    const int hA = sA / Wsp;  const int wA = sA - hA * Wsp;
    const int qbase = bA * (Cc * HWn) + hA * Wsp + wA;

    auto issue = [&](int ch) {
        const uint32_t abuf = sm_base + (uint32_t)((ch & 1) * STG_BYTES);
        const uint32_t bbuf = abuf + (uint32_t)A_BYTES;
        const int k0 = ch * KC;

#pragma unroll
        for (int j = 0; j < 16; j++) {
            const int k  = kbase + j;          // 0..31 within chunk (warp-uniform)
            const int kg = k0 + k;
            const int c  = kg / 9;
            const int t  = kg - c * 9;
            const int dh = t / 3 - 1;
            const int dw = t - (t / 3) * 3 - 1;

            // A[m][k] = x[b, c, h+dh, w+dw] (zero pad via src-size 0)
            const bool ok = (unsigned)(hA + dh) < (unsigned)Hs &&
                            (unsigned)(wA + dw) < (unsigned)Wsp;
            const float* srcA = ok ? (x + (c * HWn + dh * Wsp + dw) + qbase) : x;
            cp_async4(abuf + tile_off(lrow, k * 4), srcA, ok ? 4u : 0u);

            // Bt[n][k] = W[kg][n]; lanes read contiguous 128B of W row
            cp_async4(bbuf + tile_off(lrow, k * 4), Wm + (size_t)kg * Ff + lrow, 4u);
        }
        cp_commit();
    };

    // ---- warp MMA geometry --------------------------------------------------
    const int wm = (wid & 3) * 32;   // warp M origin (4 warps along M)
    const int wn = (wid >> 2) * 64;  // warp N origin (2 warps along N)

    float acc[2][8][4];
#pragma unroll
    for (int mt = 0; mt < 2; mt++)
#pragma unroll
        for (int nt = 0; nt < 8; nt++)
#pragma unroll
            for (int r = 0; r < 4; r++) acc[mt][nt][r] = 0.0f;

    const int a_row_l = lane & 15;
    const int a_col_l = (lane & 16) ? 16 : 0;
    const int b_row_l = (lane & 7) + ((lane & 16) ? 8 : 0);
    const int b_col_l = (lane & 8) ? 16 : 0;

    issue(0);

    for (int ch = 0; ch < NCH; ch++) {
        if (ch + 1 < NCH) issue(ch + 1);
        if (ch + 1 < NCH) cp_wait<1>(); else cp_wait<0>();
        __syncthreads();

        const uint32_t abuf = sm_base + (uint32_t)((ch & 1) * STG_BYTES);
        const uint32_t bbuf = abuf + (uint32_t)A_BYTES;

#pragma unroll
        for (int ks = 0; ks < 4; ks++) {
            uint32_t af[2][4];
#pragma unroll
            for (int mt = 0; mt < 2; mt++) {
                const int row = wm + mt * 16 + a_row_l;
                ldsm4(af[mt][0], af[mt][1], af[mt][2], af[mt][3],
                      abuf + tile_off(row, ks * 32 + a_col_l));
            }
            uint32_t bf[4][4];
#pragma unroll
            for (int tp = 0; tp < 4; tp++) {
                const int row = wn + tp * 16 + b_row_l;
                ldsm4(bf[tp][0], bf[tp][1], bf[tp][2], bf[tp][3],
                      bbuf + tile_off(row, ks * 32 + b_col_l));
            }
#pragma unroll
            for (int mt = 0; mt < 2; mt++)
#pragma unroll
                for (int nt = 0; nt < 8; nt++) {
                    const uint32_t b0 = bf[nt >> 1][(nt & 1) * 2 + 0];
                    const uint32_t b1 = bf[nt >> 1][(nt & 1) * 2 + 1];
                    mma_tf32(acc[mt][nt][0], acc[mt][nt][1],
                             acc[mt][nt][2], acc[mt][nt][3],
                             af[mt][0], af[mt][1], af[mt][2], af[mt][3],
                             b0, b1);
                }
        }
        __syncthreads();
    }

    // ---- epilogue: bias + clamp, NHWC f32 stores ---------------------------
    const int gid = lane >> 2;
    const int tig = lane & 3;
#pragma unroll
    for (int mt = 0; mt < 2; mt++) {
        const int m0 = wm + mt * 16 + gid;
        const int p0 = tile * MT + m0;
        float* o0 = out + (size_t)p0 * Ff;
        float* o1 = o0 + 8 * Ff;
#pragma unroll
        for (int nt = 0; nt < 8; nt++) {
            const int f = wn + nt * 8 + tig * 2;
            float2 v0, v1;
            v0.x = fminf(acc[mt][nt][0] + thr[f],     1.0f);
            v0.y = fminf(acc[mt][nt][1] + thr[f + 1], 1.0f);
            v1.x = fminf(acc[mt][nt][2] + thr[f],     1.0f);
            v1.y = fminf(acc[mt][nt][3] + thr[f + 1], 1.0f);
            *reinterpret_cast<float2*>(o0 + f) = v0;
            *reinterpret_cast<float2*>(o1 + f) = v1;
        }
    }
}

// ------------------------------- launcher -----------------------------------

extern "C" void kernel_launch(void* const* d_in, const int* in_sizes, int n_in,
                              void* d_out, int out_size) {
    const float* tj = (const float*)d_in[0];   // [32,128,56,56]
    const float* Wm = (const float*)d_in[1];   // [1152,128]
    const float* Di = (const float*)d_in[2];   // [9,128] (row 0 used)
    float* out = (float*)d_out;                // [32,56,56,128]

    cudaFuncSetAttribute(spiking_conv_kernel,
                         cudaFuncAttributeMaxDynamicSharedMemorySize, DSMEM);
    spiking_conv_kernel<<<GRID, 256, DSMEM>>>(tj, Wm, Di, out);
}

// round 6
// speedup vs baseline: 1.9696x; 1.6322x over previous
#include <cuda_runtime.h>
#include <cstdint>

#define DEVINL __device__ __forceinline__

// Problem shape (fixed)
static constexpr int Bn   = 32;
static constexpr int Cc   = 128;
static constexpr int Hs   = 56;
static constexpr int Wsp  = 56;
static constexpr int Ff   = 128;
static constexpr int HWn  = Hs * Wsp;      // 3136
static constexpr int Ktot = Cc * 9;        // 1152
static constexpr int KC   = 32;            // K chunk (k' = tap*128 + c order)
static constexpr int NCH  = Ktot / KC;     // 36
static constexpr int MT   = 128;           // M tile
static constexpr int Mtot = Bn * HWn;      // 100352
static constexpr int GRID = Mtot / MT;     // 784 exact

static constexpr int HP = Hs + 2;          // 58 (padded)
static constexpr int WP = Wsp + 2;         // 58

// smem: three stages of [A(128x32 f32) | B(128x32 f32)] = 3 * 32KB
static constexpr int A_BYTES   = MT * KC * 4;          // 16384
static constexpr int STG_BYTES = 2 * A_BYTES;          // 32768
static constexpr int NSTG      = 3;
static constexpr int DSMEM     = NSTG * STG_BYTES + 128;

// Scratch (allowed: __device__ globals). Zero-init -> pad borders stay zero.
__device__ float g_xT[Bn * HP * WP * Cc];   // NHWC padded, ~55 MB
__device__ float g_Wt[Ff * Ktot];           // Wt[n][k'], k' = tap*128 + c

DEVINL uint32_t smem_u32(const void* p) {
    uint32_t a;
    asm("{ .reg .u64 t; cvta.to.shared.u64 t, %1; cvt.u32.u64 %0, t; }"
        : "=r"(a) : "l"(p));
    return a;
}

DEVINL void cp_async16(uint32_t dst, const void* src) {
    asm volatile("cp.async.cg.shared.global [%0], [%1], 16;"
                 :: "r"(dst), "l"(src) : "memory");
}
DEVINL void cp_commit() { asm volatile("cp.async.commit_group;" ::: "memory"); }
template <int N> DEVINL void cp_wait() {
    asm volatile("cp.async.wait_group %0;" :: "n"(N) : "memory");
}

DEVINL void ldsm4(uint32_t& r0, uint32_t& r1, uint32_t& r2, uint32_t& r3,
                  uint32_t addr) {
    asm volatile("ldmatrix.sync.aligned.m8n8.x4.shared.b16 {%0,%1,%2,%3}, [%4];"
                 : "=r"(r0), "=r"(r1), "=r"(r2), "=r"(r3) : "r"(addr));
}

DEVINL void mma_tf32(float& d0, float& d1, float& d2, float& d3,
                     uint32_t a0, uint32_t a1, uint32_t a2, uint32_t a3,
                     uint32_t b0, uint32_t b1) {
    asm volatile(
        "mma.sync.aligned.m16n8k8.row.col.f32.tf32.tf32.f32 "
        "{%0,%1,%2,%3}, {%4,%5,%6,%7}, {%8,%9}, {%0,%1,%2,%3};"
        : "+f"(d0), "+f"(d1), "+f"(d2), "+f"(d3)
        : "r"(a0), "r"(a1), "r"(a2), "r"(a3), "r"(b0), "r"(b1));
}

// swizzled smem offset (16B granular swizzle inside 128B rows)
DEVINL uint32_t tile_off(int row, int col4) {
    return (uint32_t)(row * 128 + (col4 ^ ((row & 7) << 4)));
}

// ---------------------------------------------------------------------------
// Pre-transform 1: x[NCHW] -> g_xT[b][h+1][w+1][c]  (padded NHWC)
// smem-tiled transpose; borders never written (stay zero).
// ---------------------------------------------------------------------------
extern "C" __global__ void __launch_bounds__(256)
xpose_kernel(const float* __restrict__ x)
{
    __shared__ float s[Cc][33];
    const int bid = blockIdx.x;            // b*112 + h*2 + wt
    const int b   = bid / 112;
    const int r   = bid - b * 112;
    const int h   = r >> 1;
    const int wt  = r & 1;
    const int w0  = wt * 32;
    const int wlen = wt ? (Wsp - 32) : 32;

    const int tid = threadIdx.x;
    const int tx  = tid & 31;      // w
    const int ty  = tid >> 5;      // c step 8
    if (tx < wlen) {
#pragma unroll
        for (int c = 0; c < Cc; c += 8)
            s[c + ty][tx] = x[((b * Cc + c + ty) * HWn) + h * Wsp + w0 + tx];
    }
    __syncthreads();

    const int tc = tid & 127;      // c
    const int tw = tid >> 7;       // w step 2
    for (int w = tw; w < wlen; w += 2)
        g_xT[(((b * HP) + h + 1) * WP + (w0 + w + 1)) * Cc + tc] = s[tc][w];
}

// ---------------------------------------------------------------------------
// Pre-transform 2: W[k][n] -> g_Wt[n][k'], k = c*9+tap, k' = tap*128+c
// ---------------------------------------------------------------------------
extern "C" __global__ void __launch_bounds__(256)
wperm_kernel(const float* __restrict__ Wm)
{
    const int idx = blockIdx.x * 256 + threadIdx.x;   // over 1152*128
    const int k = idx >> 7;
    const int n = idx & 127;
    const int c = k / 9;
    const int tap = k - 9 * c;
    g_Wt[(size_t)n * Ktot + tap * Cc + c] = Wm[idx];
}

// ---------------------------------------------------------------------------
// Main: implicit-GEMM 3x3 SAME conv. CTA tile 128x128, K' chunks of 32,
// 3-stage cp.async(16B) pipeline, mma.sync tf32.
// Chunk ch: tap = ch>>2 (fixed per chunk), c0 = (ch&3)*32.
//   A row m of chunk = g_xT[b][h+1+dh][w+1+dw][c0 .. c0+32)  (contiguous 128B)
//   B row n of chunk = g_Wt[n][ch*32 .. +32)                 (contiguous 128B)
// ---------------------------------------------------------------------------
extern "C" __global__ void __launch_bounds__(256, 2)
spiking_conv_kernel(const float* __restrict__ Di, float* __restrict__ out)
{
    extern __shared__ char smraw[];
    __shared__ float thr[Ff];

    const uint32_t sm_base = (smem_u32(smraw) + 127u) & ~127u;
    const int tid  = threadIdx.x;
    const int wid  = tid >> 5;
    const int lane = tid & 31;
    const int tile = blockIdx.x;

    if (tid < Ff) thr[tid] = 1.0f - Di[tid];

    // ---- loader precompute: 4 rows per thread (row = 4*wid + 32*t + lane>>3)
    const int sub = lane >> 3;        // 0..3
    const int ch16 = lane & 7;        // 16B chunk in row
    const float* aptr[4];
#pragma unroll
    for (int t = 0; t < 4; t++) {
        const int row = 4 * wid + 32 * t + sub;
        const int p = tile * MT + row;
        const int b = p / HWn;  const int s = p - b * HWn;
        const int h = s / Wsp;  const int w = s - h * Wsp;
        aptr[t] = g_xT + (((size_t)(b * HP + h + 1) * WP) + (w + 1)) * Cc + ch16 * 4;
    }
    const int row0 = 4 * wid + sub;
    const float* bptr0 = g_Wt + (size_t)row0 * Ktot + ch16 * 4;
    const uint32_t sts0 = tile_off(row0, ch16 * 16);   // +t*4096 per t

    auto issue = [&](int ch, int stg) {
        const uint32_t abuf = sm_base + (uint32_t)(stg * STG_BYTES);
        const uint32_t bbuf = abuf + (uint32_t)A_BYTES;
        const int tap = ch >> 2;
        const int c0  = (ch & 3) << 5;
        const int dh  = tap / 3 - 1;
        const int dw  = tap - (tap / 3) * 3 - 1;
        const int aoff = (dh * WP + dw) * Cc + c0;     // floats
        const int boff = ch * KC;
#pragma unroll
        for (int t = 0; t < 4; t++)
            cp_async16(abuf + sts0 + t * 4096u, aptr[t] + aoff);
#pragma unroll
        for (int t = 0; t < 4; t++)
            cp_async16(bbuf + sts0 + t * 4096u, bptr0 + (size_t)t * 32 * Ktot + boff);
        cp_commit();
    };

    // ---- warp MMA geometry --------------------------------------------------
    const int wm = (wid & 3) * 32;   // 4 warps along M
    const int wn = (wid >> 2) * 64;  // 2 warps along N

    float acc[2][8][4];
#pragma unroll
    for (int mt = 0; mt < 2; mt++)
#pragma unroll
        for (int nt = 0; nt < 8; nt++)
#pragma unroll
            for (int rg = 0; rg < 4; rg++) acc[mt][nt][rg] = 0.0f;

    const int a_row_l = lane & 15;
    const int a_col_l = (lane & 16) ? 16 : 0;
    const int b_row_l = (lane & 7) + ((lane & 16) ? 8 : 0);
    const int b_col_l = (lane & 8) ? 16 : 0;

    issue(0, 0);
    issue(1, 1);

    int fill = 2, cons = 0;
    for (int ch = 0; ch < NCH; ch++) {
        if (ch + 2 < NCH) issue(ch + 2, fill); else cp_commit();  // keep group count
        if (++fill == NSTG) fill = 0;

        cp_wait<2>();
        __syncthreads();

        const uint32_t abuf = sm_base + (uint32_t)(cons * STG_BYTES);
        const uint32_t bbuf = abuf + (uint32_t)A_BYTES;
        if (++cons == NSTG) cons = 0;

#pragma unroll
        for (int ks = 0; ks < 4; ks++) {
            uint32_t af[2][4];
#pragma unroll
            for (int mt = 0; mt < 2; mt++) {
                const int rowa = wm + mt * 16 + a_row_l;
                ldsm4(af[mt][0], af[mt][1], af[mt][2], af[mt][3],
                      abuf + tile_off(rowa, ks * 32 + a_col_l));
            }
            uint32_t bf[4][4];
#pragma unroll
            for (int tp = 0; tp < 4; tp++) {
                const int rowb = wn + tp * 16 + b_row_l;
                ldsm4(bf[tp][0], bf[tp][1], bf[tp][2], bf[tp][3],
                      bbuf + tile_off(rowb, ks * 32 + b_col_l));
            }
#pragma unroll
            for (int mt = 0; mt < 2; mt++)
#pragma unroll
                for (int nt = 0; nt < 8; nt++) {
                    const uint32_t b0 = bf[nt >> 1][(nt & 1) * 2 + 0];
                    const uint32_t b1 = bf[nt >> 1][(nt & 1) * 2 + 1];
                    mma_tf32(acc[mt][nt][0], acc[mt][nt][1],
                             acc[mt][nt][2], acc[mt][nt][3],
                             af[mt][0], af[mt][1], af[mt][2], af[mt][3],
                             b0, b1);
                }
        }
        __syncthreads();
    }

    // ---- epilogue: bias + clamp, NHWC f32 stores ---------------------------
    const int gid = lane >> 2;
    const int tig = lane & 3;
#pragma unroll
    for (int mt = 0; mt < 2; mt++) {
        const int m0 = wm + mt * 16 + gid;
        const int p0 = tile * MT + m0;
        float* o0 = out + (size_t)p0 * Ff;
        float* o1 = o0 + 8 * Ff;
#pragma unroll
        for (int nt = 0; nt < 8; nt++) {
            const int f = wn + nt * 8 + tig * 2;
            float2 v0, v1;
            v0.x = fminf(acc[mt][nt][0] + thr[f],     1.0f);
            v0.y = fminf(acc[mt][nt][1] + thr[f + 1], 1.0f);
            v1.x = fminf(acc[mt][nt][2] + thr[f],     1.0f);
            v1.y = fminf(acc[mt][nt][3] + thr[f + 1], 1.0f);
            *reinterpret_cast<float2*>(o0 + f) = v0;
            *reinterpret_cast<float2*>(o1 + f) = v1;
        }
    }
}

// ------------------------------- launcher -----------------------------------

extern "C" void kernel_launch(void* const* d_in, const int* in_sizes, int n_in,
                              void* d_out, int out_size) {
    const float* tj = (const float*)d_in[0];   // [32,128,56,56]
    const float* Wm = (const float*)d_in[1];   // [1152,128]
    const float* Di = (const float*)d_in[2];   // [9,128] (row 0 used)
    float* out = (float*)d_out;                // [32,56,56,128]

    xpose_kernel<<<Bn * Hs * 2, 256>>>(tj);
    wperm_kernel<<<(Ktot * Ff) / 256, 256>>>(Wm);

    cudaFuncSetAttribute(spiking_conv_kernel,
                         cudaFuncAttributeMaxDynamicSharedMemorySize, DSMEM);
    spiking_conv_kernel<<<GRID, 256, DSMEM>>>(Di, out);
}

// round 7
// speedup vs baseline: 3.4640x; 1.7588x over previous
#include <cuda_runtime.h>
#include <cuda_fp16.h>
#include <cstdint>

#define DEVINL __device__ __forceinline__

// Problem shape (fixed)
static constexpr int Bn   = 32;
static constexpr int Cc   = 128;
static constexpr int Hs   = 56;
static constexpr int Wsp  = 56;
static constexpr int Ff   = 128;
static constexpr int HWn  = Hs * Wsp;      // 3136
static constexpr int Ktot = Cc * 9;        // 1152
static constexpr int KC   = 64;            // K chunk (fp16): 128B A rows
static constexpr int NCH  = Ktot / KC;     // 18
static constexpr int MT   = 128;           // M tile
static constexpr int Mtot = Bn * HWn;      // 100352
static constexpr int GRID = Mtot / MT;     // 784 exact

static constexpr int HP = Hs + 2;          // 58 (padded)
static constexpr int WP = Wsp + 2;         // 58

// smem: 3 stages of [A(128x64 fp16 = 16KB) | B(64x128 fp16 = 16KB)]
static constexpr int A_BYTES   = MT * KC * 2;          // 16384
static constexpr int B_BYTES   = KC * Ff * 2;          // 16384
static constexpr int STG_BYTES = A_BYTES + B_BYTES;    // 32768
static constexpr int NSTG      = 3;
static constexpr int DSMEM     = NSTG * STG_BYTES + 128;

// Scratch (__device__ globals; zero-init keeps pad borders zero forever)
__device__ __half g_xT[Bn * HP * WP * Cc];   // [b][h+1][w+1][c], ~27.5 MB
__device__ __half g_Wk[Ktot * Ff];           // [k'][n], k' = tap*128 + c

DEVINL uint32_t smem_u32(const void* p) {
    uint32_t a;
    asm("{ .reg .u64 t; cvta.to.shared.u64 t, %1; cvt.u32.u64 %0, t; }"
        : "=r"(a) : "l"(p));
    return a;
}

DEVINL void cp_async16(uint32_t dst, const void* src) {
    asm volatile("cp.async.cg.shared.global [%0], [%1], 16;"
                 :: "r"(dst), "l"(src) : "memory");
}
DEVINL void cp_commit() { asm volatile("cp.async.commit_group;" ::: "memory"); }
template <int N> DEVINL void cp_wait() {
    asm volatile("cp.async.wait_group %0;" :: "n"(N) : "memory");
}

DEVINL void ldsm4(uint32_t& r0, uint32_t& r1, uint32_t& r2, uint32_t& r3,
                  uint32_t addr) {
    asm volatile("ldmatrix.sync.aligned.m8n8.x4.shared.b16 {%0,%1,%2,%3}, [%4];"
                 : "=r"(r0), "=r"(r1), "=r"(r2), "=r"(r3) : "r"(addr));
}
DEVINL void ldsm4t(uint32_t& r0, uint32_t& r1, uint32_t& r2, uint32_t& r3,
                   uint32_t addr) {
    asm volatile("ldmatrix.sync.aligned.m8n8.x4.trans.shared.b16 {%0,%1,%2,%3}, [%4];"
                 : "=r"(r0), "=r"(r1), "=r"(r2), "=r"(r3) : "r"(addr));
}

DEVINL void mma_f16(float& d0, float& d1, float& d2, float& d3,
                    uint32_t a0, uint32_t a1, uint32_t a2, uint32_t a3,
                    uint32_t b0, uint32_t b1) {
    asm volatile(
        "mma.sync.aligned.m16n8k16.row.col.f32.f16.f16.f32 "
        "{%0,%1,%2,%3}, {%4,%5,%6,%7}, {%8,%9}, {%0,%1,%2,%3};"
        : "+f"(d0), "+f"(d1), "+f"(d2), "+f"(d3)
        : "r"(a0), "r"(a1), "r"(a2), "r"(a3), "r"(b0), "r"(b1));
}

// ---------------------------------------------------------------------------
// Pre-transform 1: x[NCHW] f32 -> g_xT[b][h+1][w+1][c] fp16 (padded NHWC)
// ---------------------------------------------------------------------------
extern "C" __global__ void __launch_bounds__(256)
xpose_kernel(const float* __restrict__ x)
{
    __shared__ float s[Cc][33];
    const int bid = blockIdx.x;            // b*112 + h*2 + wt
    const int b   = bid / 112;
    const int r   = bid - b * 112;
    const int h   = r >> 1;
    const int wt  = r & 1;
    const int w0  = wt * 32;
    const int wlen = wt ? (Wsp - 32) : 32;

    const int tid = threadIdx.x;
    const int tx  = tid & 31;      // w
    const int ty  = tid >> 5;      // c step 8
    if (tx < wlen) {
#pragma unroll
        for (int c = 0; c < Cc; c += 8)
            s[c + ty][tx] = x[((b * Cc + c + ty) * HWn) + h * Wsp + w0 + tx];
    }
    __syncthreads();

    const int tc = tid & 127;      // c
    const int tw = tid >> 7;       // w step 2
    for (int w = tw; w < wlen; w += 2)
        g_xT[((size_t)((b * HP) + h + 1) * WP + (w0 + w + 1)) * Cc + tc] =
            __float2half(s[tc][w]);
}

// ---------------------------------------------------------------------------
// Pre-transform 2: W[k][n] f32 -> g_Wk[k'][n] fp16, k = c*9+tap, k' = tap*128+c
// ---------------------------------------------------------------------------
extern "C" __global__ void __launch_bounds__(256)
wperm_kernel(const float* __restrict__ Wm)
{
    const int idx = blockIdx.x * 256 + threadIdx.x;   // over 1152*128
    const int k = idx >> 7;
    const int n = idx & 127;
    const int c = k / 9;
    const int tap = k - 9 * c;
    g_Wk[(size_t)(tap * Cc + c) * Ff + n] = __float2half(Wm[idx]);
}

// ---------------------------------------------------------------------------
// Main: implicit-GEMM 3x3 SAME conv, fp16 mma (fp32 accum).
// CTA tile 128x128, K' chunks of 64, 3-stage cp.async(16B) pipeline.
// Chunk ch: tap = ch>>1, c0 = (ch&1)*64.
//   A[m][0..63] = g_xT[b][h+1+dh][w+1+dw][c0..c0+64)   (contiguous 128B)
//   B[k][n]     = g_Wk[ch*64+k][n]                     (contiguous 256B rows)
// Smem swizzle: 16B chunk index XOR (row & 7).
// ---------------------------------------------------------------------------
extern "C" __global__ void __launch_bounds__(256, 2)
spiking_conv_kernel(const float* __restrict__ Di, float* __restrict__ out)
{
    extern __shared__ char smraw[];
    __shared__ float thr[Ff];

    const uint32_t sm_base = (smem_u32(smraw) + 127u) & ~127u;
    const int tid  = threadIdx.x;
    const int wid  = tid >> 5;
    const int lane = tid & 31;
    const int tile = blockIdx.x;

    if (tid < Ff) thr[tid] = 1.0f - Di[tid];

    // ---- A loader: chunk c = tid&7, rows (tid>>3) + 32*t ------------------
    const int ac = tid & 7;
    const int arow = tid >> 3;           // 0..31
    const __half* aptr[4];
#pragma unroll
    for (int t = 0; t < 4; t++) {
        const int row = arow + 32 * t;
        const int p = tile * MT + row;
        const int b = p / HWn;  const int s = p - b * HWn;
        const int h = s / Wsp;  const int w = s - h * Wsp;
        aptr[t] = g_xT + ((size_t)(b * HP + h + 1) * WP + (w + 1)) * Cc + ac * 8;
    }
    const uint32_t a_sts0 = (uint32_t)(arow * 128 + ((ac ^ (arow & 7)) * 16));

    // ---- B loader: chunk c2 = tid&15, rows (tid>>4) + 16*t ----------------
    const int bc = tid & 15;
    const int brow = tid >> 4;           // 0..15
    const __half* bptr0 = g_Wk + (size_t)brow * Ff + bc * 8;
    const uint32_t b_sts0 = (uint32_t)(brow * 256 + ((bc ^ (brow & 7)) * 16));

    auto issue = [&](int ch, int stg) {
        const uint32_t abuf = sm_base + (uint32_t)(stg * STG_BYTES);
        const uint32_t bbuf = abuf + (uint32_t)A_BYTES;
        const int tap = ch >> 1;
        const int c0  = (ch & 1) << 6;
        const int dh  = tap / 3 - 1;
        const int dw  = tap - (tap / 3) * 3 - 1;
        const int aoff = (dh * WP + dw) * Cc + c0;        // halfs
        const size_t boff = (size_t)ch * KC * Ff;         // halfs
#pragma unroll
        for (int t = 0; t < 4; t++)
            cp_async16(abuf + a_sts0 + t * 4096u, aptr[t] + aoff);
#pragma unroll
        for (int t = 0; t < 4; t++)
            cp_async16(bbuf + b_sts0 + t * 4096u, bptr0 + boff + (size_t)t * 16 * Ff);
        cp_commit();
    };

    // ---- warp MMA geometry: 4 warps M x 2 warps N, warp tile 32x64 --------
    const int wm = (wid & 3) * 32;
    const int wn = (wid >> 2) * 64;

    float acc[2][8][4];
#pragma unroll
    for (int mt = 0; mt < 2; mt++)
#pragma unroll
        for (int nt = 0; nt < 8; nt++)
#pragma unroll
            for (int rg = 0; rg < 4; rg++) acc[mt][nt][rg] = 0.0f;

    // A ldsm: row = wm + mt*16 + (lane&15); 16B chunk = ks*2 + (lane>>4)
    const int a_row_l = lane & 15;
    const int a_ch_l  = lane >> 4;
    // B ldsm (trans): j = lane>>3; krow = (j&1)*8 + (lane&7); nchunk += j>>1
    const int b_krow_l = ((lane >> 3) & 1) * 8 + (lane & 7);
    const int b_nch_l  = (lane >> 4);        // j>>1
    const int b_nch0   = (wn >> 3) + b_nch_l;

    issue(0, 0);
    issue(1, 1);

    int fill = 2, cons = 0;
    for (int ch = 0; ch < NCH; ch++) {
        if (ch + 2 < NCH) issue(ch + 2, fill); else cp_commit();
        if (++fill == NSTG) fill = 0;

        cp_wait<2>();
        __syncthreads();

        const uint32_t abuf = sm_base + (uint32_t)(cons * STG_BYTES);
        const uint32_t bbuf = abuf + (uint32_t)A_BYTES;
        if (++cons == NSTG) cons = 0;

#pragma unroll
        for (int ks = 0; ks < 4; ks++) {
            uint32_t af[2][4];
#pragma unroll
            for (int mt = 0; mt < 2; mt++) {
                const int row = wm + mt * 16 + a_row_l;
                const int chk = (ks * 2 + a_ch_l) ^ (row & 7);
                ldsm4(af[mt][0], af[mt][1], af[mt][2], af[mt][3],
                      abuf + (uint32_t)(row * 128 + chk * 16));
            }
            uint32_t bf[4][4];
#pragma unroll
            for (int nb = 0; nb < 4; nb++) {
                const int krow = ks * 16 + b_krow_l;
                const int nch  = (b_nch0 + nb * 2) ^ (b_krow_l & 7);
                ldsm4t(bf[nb][0], bf[nb][1], bf[nb][2], bf[nb][3],
                       bbuf + (uint32_t)(krow * 256 + nch * 16));
            }
#pragma unroll
            for (int mt = 0; mt < 2; mt++)
#pragma unroll
                for (int nt = 0; nt < 8; nt++) {
                    const uint32_t b0 = bf[nt >> 1][(nt & 1) * 2 + 0];
                    const uint32_t b1 = bf[nt >> 1][(nt & 1) * 2 + 1];
                    mma_f16(acc[mt][nt][0], acc[mt][nt][1],
                            acc[mt][nt][2], acc[mt][nt][3],
                            af[mt][0], af[mt][1], af[mt][2], af[mt][3],
                            b0, b1);
                }
        }
        __syncthreads();
    }

    // ---- epilogue: bias + clamp, NHWC f32 stores ---------------------------
    const int gid = lane >> 2;
    const int tig = lane & 3;
#pragma unroll
    for (int mt = 0; mt < 2; mt++) {
        const int m0 = wm + mt * 16 + gid;
        const int p0 = tile * MT + m0;
        float* o0 = out + (size_t)p0 * Ff;
        float* o1 = o0 + 8 * Ff;
#pragma unroll
        for (int nt = 0; nt < 8; nt++) {
            const int f = wn + nt * 8 + tig * 2;
            float2 v0, v1;
            v0.x = fminf(acc[mt][nt][0] + thr[f],     1.0f);
            v0.y = fminf(acc[mt][nt][1] + thr[f + 1], 1.0f);
            v1.x = fminf(acc[mt][nt][2] + thr[f],     1.0f);
            v1.y = fminf(acc[mt][nt][3] + thr[f + 1], 1.0f);
            *reinterpret_cast<float2*>(o0 + f) = v0;
            *reinterpret_cast<float2*>(o1 + f) = v1;
        }
    }
}

// ------------------------------- launcher -----------------------------------

extern "C" void kernel_launch(void* const* d_in, const int* in_sizes, int n_in,
                              void* d_out, int out_size) {
    const float* tj = (const float*)d_in[0];   // [32,128,56,56]
    const float* Wm = (const float*)d_in[1];   // [1152,128]
    const float* Di = (const float*)d_in[2];   // [9,128] (row 0 used)
    float* out = (float*)d_out;                // [32,56,56,128]

    xpose_kernel<<<Bn * Hs * 2, 256>>>(tj);
    wperm_kernel<<<(Ktot * Ff) / 256, 256>>>(Wm);

    cudaFuncSetAttribute(spiking_conv_kernel,
                         cudaFuncAttributeMaxDynamicSharedMemorySize, DSMEM);
    spiking_conv_kernel<<<GRID, 256, DSMEM>>>(Di, out);
}